// round 14
// baseline (speedup 1.0000x reference)
#include <cuda_runtime.h>
#include <cuda_fp16.h>
#include <math.h>
#include <stdint.h>

#define BATCH 8
#define NTOK  2048
#define FDIM  64
#define ALPHA 0.2f

// ---------------- scratch (__device__ globals; no allocs allowed) ----------
__device__ __align__(16) __half g_WhT[BATCH * FDIM * NTOK];  // [b][o][j] fp16
__device__ float g_ssrc[BATCH * NTOK];
__device__ float g_sdst[BATCH * NTOK];
__device__ __align__(16) __half g_uh[BATCH * NTOK];          // e^(sd-M)   fp16
__device__ __align__(16) __half g_vh[BATCH * NTOK];          // e^(a(sd-M)) fp16
__device__ float g_maxs[BATCH];

__device__ __forceinline__ float eluf(float x) { return x > 0.f ? x : expm1f(x); }

__device__ __forceinline__ uint32_t smem_u32(const void* p) {
    uint32_t a;
    asm("{ .reg .u64 t; cvta.to.shared.u64 t, %1; cvt.u32.u64 %0, t; }" : "=r"(a) : "l"(p));
    return a;
}

__device__ __forceinline__ uint32_t h2u(__half2 h) {
    uint32_t r;
    asm("mov.b32 %0, %1;" : "=r"(r) : "r"(*(uint32_t*)&h));
    return r;
}

__device__ __forceinline__ void cp16(uint32_t dst, const void* src) {
    asm volatile("cp.async.cg.shared.global [%0], [%1], 16;" :: "r"(dst), "l"(src));
}
#define CP_COMMIT() asm volatile("cp.async.commit_group;" ::: "memory")
#define CP_WAIT0()  asm volatile("cp.async.wait_group 0;" ::: "memory")

__device__ __forceinline__ void mma_f16(float* d, uint32_t a0, uint32_t a1,
                                        uint32_t a2, uint32_t a3,
                                        uint32_t b0, uint32_t b1) {
    asm volatile(
        "mma.sync.aligned.m16n8k16.row.col.f32.f16.f16.f32 "
        "{%0,%1,%2,%3}, {%4,%5,%6,%7}, {%8,%9}, {%0,%1,%2,%3};"
        : "+f"(d[0]), "+f"(d[1]), "+f"(d[2]), "+f"(d[3])
        : "r"(a0), "r"(a1), "r"(a2), "r"(a3), "r"(b0), "r"(b1));
}

__device__ __forceinline__ void ldm_x4(uint32_t* r, uint32_t addr) {
    asm volatile("ldmatrix.sync.aligned.m8n8.x4.shared.b16 {%0,%1,%2,%3}, [%4];"
                 : "=r"(r[0]), "=r"(r[1]), "=r"(r[2]), "=r"(r[3]) : "r"(addr));
}

// ---------------------------------------------------------------------------
// Kernel 1: Wh via fp16 HMMA; exact fp32 scores s=h.(W@a).
//   NOW 128 rows/CTA, 256 thr, 8 warps, grid 128 (2x warps/SM vs R13).
// ---------------------------------------------------------------------------
__global__ void __launch_bounds__(256) k1_proj(const float* __restrict__ h,
                                               const float* __restrict__ W,
                                               const float* __restrict__ a) {
    __shared__ float a_s[128];
    __shared__ float2 Wa_s[64];
    __shared__ __align__(16) __half WT_s[64 * 72];    // [o][k]   9216 B
    __shared__ __align__(16) __half h_s[128 * 72];    // [j][k]  18432 B
    __shared__ __align__(16) __half T_s[64 * 136];    // [o][j]  17408 B

    int tid = threadIdx.x;
    int row0 = blockIdx.x * 128;
    int bb = row0 >> 11;
    int jbase = row0 & 2047;

    if (tid < 128) a_s[tid] = a[tid];
    __syncthreads();

    // ---- W transpose (fp16) + Wa = W @ a: 4 threads per k-row ----
    {
        int k = tid >> 2, qd = tid & 3;
        const float4* wr = (const float4*)(W + k * 64 + qd * 16);
        float pws = 0.f, pwd = 0.f;
#pragma unroll
        for (int f = 0; f < 4; f++) {
            float4 v = wr[f];
            int o = qd * 16 + f * 4;
            WT_s[(o + 0) * 72 + k] = __float2half(v.x);
            WT_s[(o + 1) * 72 + k] = __float2half(v.y);
            WT_s[(o + 2) * 72 + k] = __float2half(v.z);
            WT_s[(o + 3) * 72 + k] = __float2half(v.w);
            pws += v.x * a_s[o] + v.y * a_s[o + 1] + v.z * a_s[o + 2] + v.w * a_s[o + 3];
            pwd += v.x * a_s[64 + o] + v.y * a_s[65 + o] + v.z * a_s[66 + o] + v.w * a_s[67 + o];
        }
        pws += __shfl_xor_sync(0xffffffffu, pws, 1);
        pwd += __shfl_xor_sync(0xffffffffu, pwd, 1);
        pws += __shfl_xor_sync(0xffffffffu, pws, 2);
        pwd += __shfl_xor_sync(0xffffffffu, pwd, 2);
        if (qd == 0) Wa_s[k] = make_float2(pws, pwd);
    }

    // ---- h load (fp32) : 2 threads per row, 128 rows ----
    int r = tid >> 1, hf = tid & 1;
    float4 hv[8];
    {
        const float4* hrow = (const float4*)(h + (size_t)(row0 + r) * 64 + hf * 32);
#pragma unroll
        for (int f = 0; f < 8; f++) hv[f] = hrow[f];
    }
    __syncthreads();   // Wa_s, WT_s ready

    // ---- exact dots + fp16 h_s store ----
    {
        float ps = 0.f, pd = 0.f;
        __half2* hs2 = (__half2*)(h_s + r * 72 + hf * 32);
#pragma unroll
        for (int f = 0; f < 8; f++) {
            float4 v = hv[f];
            int k = hf * 32 + f * 4;
            float2 w0 = Wa_s[k], w1 = Wa_s[k + 1], w2 = Wa_s[k + 2], w3 = Wa_s[k + 3];
            ps += v.x * w0.x + v.y * w1.x + v.z * w2.x + v.w * w3.x;
            pd += v.x * w0.y + v.y * w1.y + v.z * w2.y + v.w * w3.y;
            hs2[f * 2]     = __floats2half2_rn(v.x, v.y);
            hs2[f * 2 + 1] = __floats2half2_rn(v.z, v.w);
        }
        ps += __shfl_xor_sync(0xffffffffu, ps, 1);
        pd += __shfl_xor_sync(0xffffffffu, pd, 1);
        if (hf == 0) {
            g_ssrc[row0 + r] = ps;
            g_sdst[row0 + r] = pd;
        }
    }
    __syncthreads();

    // ---- MMA: 8 warps x 16 rows ----
    int w = tid >> 5, lane = tid & 31;
    uint32_t hs_b = smem_u32(h_s);
    uint32_t wt_b = smem_u32(WT_s);
    uint32_t aoff = ((w * 16 + ((lane >> 3) & 1) * 8 + (lane & 7)) * 36 +
                     ((lane >> 4) & 1) * 4) * 4;
    uint32_t boff = ((((lane >> 4) & 1) * 8 + (lane & 7)) * 36 +
                     ((lane >> 3) & 1) * 4) * 4;

    float acc[8][4];
#pragma unroll
    for (int n = 0; n < 8; n++)
#pragma unroll
        for (int i = 0; i < 4; i++) acc[n][i] = 0.f;

#pragma unroll
    for (int kk = 0; kk < 4; kk++) {
        uint32_t av[4];
        ldm_x4(av, hs_b + aoff + kk * 32);
#pragma unroll
        for (int nn = 0; nn < 4; nn++) {
            uint32_t bv[4];
            ldm_x4(bv, wt_b + boff + nn * 2304 + kk * 32);
            mma_f16(acc[2 * nn],     av[0], av[1], av[2], av[3], bv[0], bv[1]);
            mma_f16(acc[2 * nn + 1], av[0], av[1], av[2], av[3], bv[2], bv[3]);
        }
    }

    // ---- transpose acc -> T_s[o][j] (stride 136 halfs) ----
    {
        int q = lane >> 2, c4 = lane & 3;
        int jr = w * 16 + q;
#pragma unroll
        for (int n = 0; n < 8; n++) {
            int o = n * 8 + 2 * c4;
            T_s[o * 136 + jr]           = __float2half(acc[n][0]);
            T_s[(o + 1) * 136 + jr]     = __float2half(acc[n][1]);
            T_s[o * 136 + jr + 8]       = __float2half(acc[n][2]);
            T_s[(o + 1) * 136 + jr + 8] = __float2half(acc[n][3]);
        }
    }
    __syncthreads();

    // ---- coalesced WhT store: 1024 uint4 ----
    {
        const uint4* T4 = (const uint4*)T_s;          // row stride 17 uint4
        uint4* dst = (uint4*)(g_WhT + (size_t)bb * FDIM * NTOK + jbase);
#pragma unroll
        for (int it = 0; it < 4; it++) {
            int idx = tid + it * 256;
            int o = idx >> 4, u4 = idx & 15;
            dst[o * 256 + u4] = T4[o * 17 + u4];
        }
    }
}

// ---------------------------------------------------------------------------
// Kernel 2: per-batch max of s_dst AND fp16 u~/v~ tables.  512 thr.
// ---------------------------------------------------------------------------
__global__ void __launch_bounds__(512) k2_prep() {
    __shared__ float red[16];
    __shared__ float sM;
    int b = blockIdx.x, tid = threadIdx.x;
    float m = -1e30f;
    for (int j = tid; j < NTOK; j += 512) m = fmaxf(m, g_sdst[b * NTOK + j]);
#pragma unroll
    for (int o = 16; o > 0; o >>= 1)
        m = fmaxf(m, __shfl_xor_sync(0xffffffffu, m, o));
    if ((tid & 31) == 0) red[tid >> 5] = m;
    __syncthreads();
    if (tid == 0) {
        float r = red[0];
#pragma unroll
        for (int i = 1; i < 16; i++) r = fmaxf(r, red[i]);
        sM = r;
        g_maxs[b] = r;
    }
    __syncthreads();
    float M = sM;
    for (int j = tid; j < NTOK; j += 512) {
        float d = g_sdst[b * NTOK + j] - M;
        g_uh[b * NTOK + j] = __float2half(expf(d));
        g_vh[b * NTOK + j] = __float2half(expf(ALPHA * d));
    }
}

// ---------------------------------------------------------------------------
// Kernel 3: fused attention.  NO ones-column: Z accumulated exactly in fp32
// from the fp16 p-words (ALU pipe; tensor work -11%).  256-j tiles, cp.async,
// one barrier/tile.  128 CTAs, 512 thr = 4 m-warps x 4 j-split.
// ---------------------------------------------------------------------------
#define STRIDE_W  132                      // words per o-row (256 halfs + pad)
#define TBB       (64 * STRIDE_W * 4)      // 33792 B per buffer
#define UOFF      (2 * TBB)
#define VOFF      (UOFF + 4096)
#define SMEM3_TOTAL (VOFF + 4096)

__global__ void __launch_bounds__(512, 1) k3_attn(float* __restrict__ out) {
    extern __shared__ char smem[];
    uint32_t sb = smem_u32(smem);
    const __half2* u2_s = (const __half2*)(smem + UOFF);
    const __half2* v2_s = (const __half2*)(smem + VOFF);

    int tid = threadIdx.x;
    int lane = tid & 31;
    int wid = tid >> 5;
    int mw = wid & 3, js = wid >> 2;
    int b = blockIdx.y;
    int i0 = blockIdx.x * 128;

    if (tid < 256) {
        const uint4* ug = (const uint4*)(g_uh + b * NTOK);
        const uint4* vg = (const uint4*)(g_vh + b * NTOK);
        ((uint4*)(smem + UOFF))[tid] = ug[tid];
        ((uint4*)(smem + VOFF))[tid] = vg[tid];
    }

    int q = lane >> 2, c4 = lane & 3;
    int rbase = i0 + mw * 32 + q;
    float M = g_maxs[b];
    __half2 A2[4], B2[4];
#pragma unroll
    for (int rr = 0; rr < 4; rr++) {
        float t = g_ssrc[b * NTOK + rbase + rr * 8] + M;
        float mi = t > 0.f ? t : ALPHA * t;
        A2[rr] = __float2half2_rn(expf(t - mi));
        B2[rr] = __float2half2_rn(expf(ALPHA * t - mi));
    }

    float acc[2][8][4];
    float z[4] = {0.f, 0.f, 0.f, 0.f};
#pragma unroll
    for (int mt = 0; mt < 2; mt++)
#pragma unroll
        for (int n = 0; n < 8; n++)
#pragma unroll
            for (int i = 0; i < 4; i++) acc[mt][n][i] = 0.f;

    uint32_t row_off = ((((lane >> 4) & 1) * 8 + (lane & 7)) * (uint32_t)STRIDE_W) +
                       ((lane >> 3) & 1) * 4u;

    const uint4* WhT4 = (const uint4*)(g_WhT + (size_t)b * FDIM * NTOK);
    int so = tid >> 5, su = tid & 31;

    // prologue: tile 0 via cp.async
#pragma unroll
    for (int it = 0; it < 4; it++) {
        int o = so + it * 16;
        cp16(sb + (uint32_t)(o * STRIDE_W + su * 4) * 4, WhT4 + o * 256 + su);
    }
    CP_COMMIT();

    for (int t = 0; t < 8; t++) {
        CP_WAIT0();
        __syncthreads();

        if (t < 7) {
            uint32_t nb = sb + ((t + 1) & 1) * (uint32_t)TBB;
#pragma unroll
            for (int it = 0; it < 4; it++) {
                int o = so + it * 16;
                cp16(nb + (uint32_t)(o * STRIDE_W + su * 4) * 4,
                     WhT4 + o * 256 + (t + 1) * 32 + su);
            }
            CP_COMMIT();
        }

        uint32_t cur = sb + (t & 1) * (uint32_t)TBB;
#pragma unroll
        for (int cc = 0; cc < 4; cc++) {
            int c = js * 4 + cc;
            int cb2 = t * 128 + c * 8;
            __half2 ua = u2_s[cb2 + c4];
            __half2 ub = u2_s[cb2 + 4 + c4];
            __half2 va = v2_s[cb2 + c4];
            __half2 vb = v2_s[cb2 + 4 + c4];
            uint32_t af[2][4];
#pragma unroll
            for (int mt = 0; mt < 2; mt++) {
                int r0 = mt * 2, r1 = mt * 2 + 1;
                __half2 p0 = __hmax2(__hmul2(A2[r0], ua), __hmul2(B2[r0], va));
                __half2 p1 = __hmax2(__hmul2(A2[r1], ua), __hmul2(B2[r1], va));
                __half2 p2 = __hmax2(__hmul2(A2[r0], ub), __hmul2(B2[r0], vb));
                __half2 p3 = __hmax2(__hmul2(A2[r1], ub), __hmul2(B2[r1], vb));
                float2 q0 = __half22float2(p0), q2 = __half22float2(p2);
                z[r0] += (q0.x + q0.y) + (q2.x + q2.y);
                float2 q1 = __half22float2(p1), q3 = __half22float2(p3);
                z[r1] += (q1.x + q1.y) + (q3.x + q3.y);
                af[mt][0] = h2u(p0);
                af[mt][1] = h2u(p1);
                af[mt][2] = h2u(p2);
                af[mt][3] = h2u(p3);
            }
            uint32_t bf[4][4];
            uint32_t base = cur + (row_off + (uint32_t)c * 8) * 4;
#pragma unroll
            for (int nn = 0; nn < 4; nn++)
                ldm_x4(bf[nn], base + (uint32_t)nn * (16u * STRIDE_W * 4u));
#pragma unroll
            for (int n = 0; n < 8; n++) {
                uint32_t b0 = bf[n >> 1][(n & 1) * 2];
                uint32_t b1 = bf[n >> 1][(n & 1) * 2 + 1];
                mma_f16(acc[0][n], af[0][0], af[0][1], af[0][2], af[0][3], b0, b1);
                mma_f16(acc[1][n], af[1][0], af[1][1], af[1][2], af[1][3], b0, b1);
            }
        }
    }
    __syncthreads();

    // ---- reduce across js groups (128 slots, stride 69, payload 64+4z) ----
    float* red = (float*)smem;
    int slot = mw * 32 + lane;
    float* accf = &acc[0][0][0];
#pragma unroll
    for (int src = 1; src < 4; src++) {
        if (js == src) {
#pragma unroll
            for (int i = 0; i < 64; i++) red[slot * 69 + i] = accf[i];
#pragma unroll
            for (int i = 0; i < 4; i++) red[slot * 69 + 64 + i] = z[i];
        }
        __syncthreads();
        if (js == 0) {
#pragma unroll
            for (int i = 0; i < 64; i++) accf[i] += red[slot * 69 + i];
#pragma unroll
            for (int i = 0; i < 4; i++) z[i] += red[slot * 69 + 64 + i];
        }
        __syncthreads();
    }

    // ---- epilogue (js == 0) ----
    if (js == 0) {
        // finish Z across the c4 quad (j-coverage per lane: 4 of 16 per chunk)
#pragma unroll
        for (int rr = 0; rr < 4; rr++) {
            z[rr] += __shfl_xor_sync(0xffffffffu, z[rr], 1);
            z[rr] += __shfl_xor_sync(0xffffffffu, z[rr], 2);
        }
        float inv0 = 1.f / z[0], inv1 = 1.f / z[1];
        float inv2 = 1.f / z[2], inv3 = 1.f / z[3];

        float* o0 = out + ((size_t)(b * NTOK + rbase)) * 64 + 2 * c4;
        float* o1 = o0 + 8 * 64;
        float* o2 = o0 + 16 * 64;
        float* o3 = o0 + 24 * 64;
#pragma unroll
        for (int n = 0; n < 8; n++) {
            float2 w0, w1, w2, w3;
            w0.x = eluf(acc[0][n][0] * inv0);
            w0.y = eluf(acc[0][n][1] * inv0);
            w1.x = eluf(acc[0][n][2] * inv1);
            w1.y = eluf(acc[0][n][3] * inv1);
            w2.x = eluf(acc[1][n][0] * inv2);
            w2.y = eluf(acc[1][n][1] * inv2);
            w3.x = eluf(acc[1][n][2] * inv3);
            w3.y = eluf(acc[1][n][3] * inv3);
            *(float2*)(o0 + n * 8) = w0;
            *(float2*)(o1 + n * 8) = w1;
            *(float2*)(o2 + n * 8) = w2;
            *(float2*)(o3 + n * 8) = w3;
        }
    }
}

// ---------------------------------------------------------------------------
extern "C" void kernel_launch(void* const* d_in, const int* in_sizes, int n_in,
                              void* d_out, int out_size) {
    const float* h = (const float*)d_in[0];
    const float* W = (const float*)d_in[1];
    const float* a = (const float*)d_in[2];
    float* out = (float*)d_out;

    cudaFuncSetAttribute(k3_attn, cudaFuncAttributeMaxDynamicSharedMemorySize,
                         SMEM3_TOTAL);

    k1_proj<<<(BATCH * NTOK) / 128, 256>>>(h, W, a);
    k2_prep<<<BATCH, 512>>>();
    dim3 g3(NTOK / 128, BATCH);
    k3_attn<<<g3, 512, SMEM3_TOTAL>>>(out);
}

// round 15
// speedup vs baseline: 1.0009x; 1.0009x over previous
#include <cuda_runtime.h>
#include <cuda_fp16.h>
#include <math.h>
#include <stdint.h>

#define BATCH 8
#define NTOK  2048
#define FDIM  64
#define ALPHA 0.2f

// ---------------- scratch (__device__ globals; no allocs allowed) ----------
__device__ __align__(16) __half g_WhT[BATCH * FDIM * NTOK];  // [b][o][j] fp16
__device__ float g_ssrc[BATCH * NTOK];
__device__ float g_sdst[BATCH * NTOK];
__device__ __align__(16) __half g_uh[BATCH * NTOK];          // e^(sd-M)   fp16
__device__ __align__(16) __half g_vh[BATCH * NTOK];          // e^(a(sd-M)) fp16
__device__ float g_maxs[BATCH];

__device__ __forceinline__ float eluf(float x) { return x > 0.f ? x : expm1f(x); }

__device__ __forceinline__ uint32_t smem_u32(const void* p) {
    uint32_t a;
    asm("{ .reg .u64 t; cvta.to.shared.u64 t, %1; cvt.u32.u64 %0, t; }" : "=r"(a) : "l"(p));
    return a;
}

__device__ __forceinline__ uint32_t h2u(__half2 h) {
    uint32_t r;
    asm("mov.b32 %0, %1;" : "=r"(r) : "r"(*(uint32_t*)&h));
    return r;
}

__device__ __forceinline__ void cp16(uint32_t dst, const void* src) {
    asm volatile("cp.async.cg.shared.global [%0], [%1], 16;" :: "r"(dst), "l"(src));
}
#define CP_COMMIT() asm volatile("cp.async.commit_group;" ::: "memory")
#define CP_WAIT0()  asm volatile("cp.async.wait_group 0;" ::: "memory")

__device__ __forceinline__ void mma_f16(float* d, uint32_t a0, uint32_t a1,
                                        uint32_t a2, uint32_t a3,
                                        uint32_t b0, uint32_t b1) {
    asm volatile(
        "mma.sync.aligned.m16n8k16.row.col.f32.f16.f16.f32 "
        "{%0,%1,%2,%3}, {%4,%5,%6,%7}, {%8,%9}, {%0,%1,%2,%3};"
        : "+f"(d[0]), "+f"(d[1]), "+f"(d[2]), "+f"(d[3])
        : "r"(a0), "r"(a1), "r"(a2), "r"(a3), "r"(b0), "r"(b1));
}

__device__ __forceinline__ void ldm_x4(uint32_t* r, uint32_t addr) {
    asm volatile("ldmatrix.sync.aligned.m8n8.x4.shared.b16 {%0,%1,%2,%3}, [%4];"
                 : "=r"(r[0]), "=r"(r[1]), "=r"(r[2]), "=r"(r[3]) : "r"(addr));
}

// ---------------------------------------------------------------------------
// Kernel 1: Wh via fp16 HMMA; exact fp32 scores s=h.(W@a).
//   NOW 128 rows/CTA, 256 thr, 8 warps, grid 128 (2x warps/SM vs R13).
// ---------------------------------------------------------------------------
__global__ void __launch_bounds__(256) k1_proj(const float* __restrict__ h,
                                               const float* __restrict__ W,
                                               const float* __restrict__ a) {
    __shared__ float a_s[128];
    __shared__ float2 Wa_s[64];
    __shared__ __align__(16) __half WT_s[64 * 72];    // [o][k]   9216 B
    __shared__ __align__(16) __half h_s[128 * 72];    // [j][k]  18432 B
    __shared__ __align__(16) __half T_s[64 * 136];    // [o][j]  17408 B

    int tid = threadIdx.x;
    int row0 = blockIdx.x * 128;
    int bb = row0 >> 11;
    int jbase = row0 & 2047;

    if (tid < 128) a_s[tid] = a[tid];
    __syncthreads();

    // ---- W transpose (fp16) + Wa = W @ a: 4 threads per k-row ----
    {
        int k = tid >> 2, qd = tid & 3;
        const float4* wr = (const float4*)(W + k * 64 + qd * 16);
        float pws = 0.f, pwd = 0.f;
#pragma unroll
        for (int f = 0; f < 4; f++) {
            float4 v = wr[f];
            int o = qd * 16 + f * 4;
            WT_s[(o + 0) * 72 + k] = __float2half(v.x);
            WT_s[(o + 1) * 72 + k] = __float2half(v.y);
            WT_s[(o + 2) * 72 + k] = __float2half(v.z);
            WT_s[(o + 3) * 72 + k] = __float2half(v.w);
            pws += v.x * a_s[o] + v.y * a_s[o + 1] + v.z * a_s[o + 2] + v.w * a_s[o + 3];
            pwd += v.x * a_s[64 + o] + v.y * a_s[65 + o] + v.z * a_s[66 + o] + v.w * a_s[67 + o];
        }
        pws += __shfl_xor_sync(0xffffffffu, pws, 1);
        pwd += __shfl_xor_sync(0xffffffffu, pwd, 1);
        pws += __shfl_xor_sync(0xffffffffu, pws, 2);
        pwd += __shfl_xor_sync(0xffffffffu, pwd, 2);
        if (qd == 0) Wa_s[k] = make_float2(pws, pwd);
    }

    // ---- h load (fp32) : 2 threads per row, 128 rows ----
    int r = tid >> 1, hf = tid & 1;
    float4 hv[8];
    {
        const float4* hrow = (const float4*)(h + (size_t)(row0 + r) * 64 + hf * 32);
#pragma unroll
        for (int f = 0; f < 8; f++) hv[f] = hrow[f];
    }
    __syncthreads();   // Wa_s, WT_s ready

    // ---- exact dots + fp16 h_s store ----
    {
        float ps = 0.f, pd = 0.f;
        __half2* hs2 = (__half2*)(h_s + r * 72 + hf * 32);
#pragma unroll
        for (int f = 0; f < 8; f++) {
            float4 v = hv[f];
            int k = hf * 32 + f * 4;
            float2 w0 = Wa_s[k], w1 = Wa_s[k + 1], w2 = Wa_s[k + 2], w3 = Wa_s[k + 3];
            ps += v.x * w0.x + v.y * w1.x + v.z * w2.x + v.w * w3.x;
            pd += v.x * w0.y + v.y * w1.y + v.z * w2.y + v.w * w3.y;
            hs2[f * 2]     = __floats2half2_rn(v.x, v.y);
            hs2[f * 2 + 1] = __floats2half2_rn(v.z, v.w);
        }
        ps += __shfl_xor_sync(0xffffffffu, ps, 1);
        pd += __shfl_xor_sync(0xffffffffu, pd, 1);
        if (hf == 0) {
            g_ssrc[row0 + r] = ps;
            g_sdst[row0 + r] = pd;
        }
    }
    __syncthreads();

    // ---- MMA: 8 warps x 16 rows ----
    int w = tid >> 5, lane = tid & 31;
    uint32_t hs_b = smem_u32(h_s);
    uint32_t wt_b = smem_u32(WT_s);
    uint32_t aoff = ((w * 16 + ((lane >> 3) & 1) * 8 + (lane & 7)) * 36 +
                     ((lane >> 4) & 1) * 4) * 4;
    uint32_t boff = ((((lane >> 4) & 1) * 8 + (lane & 7)) * 36 +
                     ((lane >> 3) & 1) * 4) * 4;

    float acc[8][4];
#pragma unroll
    for (int n = 0; n < 8; n++)
#pragma unroll
        for (int i = 0; i < 4; i++) acc[n][i] = 0.f;

#pragma unroll
    for (int kk = 0; kk < 4; kk++) {
        uint32_t av[4];
        ldm_x4(av, hs_b + aoff + kk * 32);
#pragma unroll
        for (int nn = 0; nn < 4; nn++) {
            uint32_t bv[4];
            ldm_x4(bv, wt_b + boff + nn * 2304 + kk * 32);
            mma_f16(acc[2 * nn],     av[0], av[1], av[2], av[3], bv[0], bv[1]);
            mma_f16(acc[2 * nn + 1], av[0], av[1], av[2], av[3], bv[2], bv[3]);
        }
    }

    // ---- transpose acc -> T_s[o][j] (stride 136 halfs) ----
    {
        int q = lane >> 2, c4 = lane & 3;
        int jr = w * 16 + q;
#pragma unroll
        for (int n = 0; n < 8; n++) {
            int o = n * 8 + 2 * c4;
            T_s[o * 136 + jr]           = __float2half(acc[n][0]);
            T_s[(o + 1) * 136 + jr]     = __float2half(acc[n][1]);
            T_s[o * 136 + jr + 8]       = __float2half(acc[n][2]);
            T_s[(o + 1) * 136 + jr + 8] = __float2half(acc[n][3]);
        }
    }
    __syncthreads();

    // ---- coalesced WhT store: 1024 uint4 ----
    {
        const uint4* T4 = (const uint4*)T_s;          // row stride 17 uint4
        uint4* dst = (uint4*)(g_WhT + (size_t)bb * FDIM * NTOK + jbase);
#pragma unroll
        for (int it = 0; it < 4; it++) {
            int idx = tid + it * 256;
            int o = idx >> 4, u4 = idx & 15;
            dst[o * 256 + u4] = T4[o * 17 + u4];
        }
    }
}

// ---------------------------------------------------------------------------
// Kernel 2: per-batch max of s_dst AND fp16 u~/v~ tables.  512 thr.
// ---------------------------------------------------------------------------
__global__ void __launch_bounds__(512) k2_prep() {
    __shared__ float red[16];
    __shared__ float sM;
    int b = blockIdx.x, tid = threadIdx.x;
    float m = -1e30f;
    for (int j = tid; j < NTOK; j += 512) m = fmaxf(m, g_sdst[b * NTOK + j]);
#pragma unroll
    for (int o = 16; o > 0; o >>= 1)
        m = fmaxf(m, __shfl_xor_sync(0xffffffffu, m, o));
    if ((tid & 31) == 0) red[tid >> 5] = m;
    __syncthreads();
    if (tid == 0) {
        float r = red[0];
#pragma unroll
        for (int i = 1; i < 16; i++) r = fmaxf(r, red[i]);
        sM = r;
        g_maxs[b] = r;
    }
    __syncthreads();
    float M = sM;
    for (int j = tid; j < NTOK; j += 512) {
        float d = g_sdst[b * NTOK + j] - M;
        g_uh[b * NTOK + j] = __float2half(expf(d));
        g_vh[b * NTOK + j] = __float2half(expf(ALPHA * d));
    }
}

// ---------------------------------------------------------------------------
// Kernel 3: fused attention.  NO ones-column: Z accumulated exactly in fp32
// from the fp16 p-words (ALU pipe; tensor work -11%).  256-j tiles, cp.async,
// one barrier/tile.  128 CTAs, 512 thr = 4 m-warps x 4 j-split.
// ---------------------------------------------------------------------------
#define STRIDE_W  132                      // words per o-row (256 halfs + pad)
#define TBB       (64 * STRIDE_W * 4)      // 33792 B per buffer
#define UOFF      (2 * TBB)
#define VOFF      (UOFF + 4096)
#define SMEM3_TOTAL (VOFF + 4096)

__global__ void __launch_bounds__(512, 1) k3_attn(float* __restrict__ out) {
    extern __shared__ char smem[];
    uint32_t sb = smem_u32(smem);
    const __half2* u2_s = (const __half2*)(smem + UOFF);
    const __half2* v2_s = (const __half2*)(smem + VOFF);

    int tid = threadIdx.x;
    int lane = tid & 31;
    int wid = tid >> 5;
    int mw = wid & 3, js = wid >> 2;
    int b = blockIdx.y;
    int i0 = blockIdx.x * 128;

    if (tid < 256) {
        const uint4* ug = (const uint4*)(g_uh + b * NTOK);
        const uint4* vg = (const uint4*)(g_vh + b * NTOK);
        ((uint4*)(smem + UOFF))[tid] = ug[tid];
        ((uint4*)(smem + VOFF))[tid] = vg[tid];
    }

    int q = lane >> 2, c4 = lane & 3;
    int rbase = i0 + mw * 32 + q;
    float M = g_maxs[b];
    __half2 A2[4], B2[4];
#pragma unroll
    for (int rr = 0; rr < 4; rr++) {
        float t = g_ssrc[b * NTOK + rbase + rr * 8] + M;
        float mi = t > 0.f ? t : ALPHA * t;
        A2[rr] = __float2half2_rn(expf(t - mi));
        B2[rr] = __float2half2_rn(expf(ALPHA * t - mi));
    }

    float acc[2][8][4];
    float z[4] = {0.f, 0.f, 0.f, 0.f};
#pragma unroll
    for (int mt = 0; mt < 2; mt++)
#pragma unroll
        for (int n = 0; n < 8; n++)
#pragma unroll
            for (int i = 0; i < 4; i++) acc[mt][n][i] = 0.f;

    uint32_t row_off = ((((lane >> 4) & 1) * 8 + (lane & 7)) * (uint32_t)STRIDE_W) +
                       ((lane >> 3) & 1) * 4u;

    const uint4* WhT4 = (const uint4*)(g_WhT + (size_t)b * FDIM * NTOK);
    int so = tid >> 5, su = tid & 31;

    // prologue: tile 0 via cp.async
#pragma unroll
    for (int it = 0; it < 4; it++) {
        int o = so + it * 16;
        cp16(sb + (uint32_t)(o * STRIDE_W + su * 4) * 4, WhT4 + o * 256 + su);
    }
    CP_COMMIT();

    for (int t = 0; t < 8; t++) {
        CP_WAIT0();
        __syncthreads();

        if (t < 7) {
            uint32_t nb = sb + ((t + 1) & 1) * (uint32_t)TBB;
#pragma unroll
            for (int it = 0; it < 4; it++) {
                int o = so + it * 16;
                cp16(nb + (uint32_t)(o * STRIDE_W + su * 4) * 4,
                     WhT4 + o * 256 + (t + 1) * 32 + su);
            }
            CP_COMMIT();
        }

        uint32_t cur = sb + (t & 1) * (uint32_t)TBB;
#pragma unroll
        for (int cc = 0; cc < 4; cc++) {
            int c = js * 4 + cc;
            int cb2 = t * 128 + c * 8;
            __half2 ua = u2_s[cb2 + c4];
            __half2 ub = u2_s[cb2 + 4 + c4];
            __half2 va = v2_s[cb2 + c4];
            __half2 vb = v2_s[cb2 + 4 + c4];
            uint32_t af[2][4];
#pragma unroll
            for (int mt = 0; mt < 2; mt++) {
                int r0 = mt * 2, r1 = mt * 2 + 1;
                __half2 p0 = __hmax2(__hmul2(A2[r0], ua), __hmul2(B2[r0], va));
                __half2 p1 = __hmax2(__hmul2(A2[r1], ua), __hmul2(B2[r1], va));
                __half2 p2 = __hmax2(__hmul2(A2[r0], ub), __hmul2(B2[r0], vb));
                __half2 p3 = __hmax2(__hmul2(A2[r1], ub), __hmul2(B2[r1], vb));
                float2 q0 = __half22float2(p0), q2 = __half22float2(p2);
                z[r0] += (q0.x + q0.y) + (q2.x + q2.y);
                float2 q1 = __half22float2(p1), q3 = __half22float2(p3);
                z[r1] += (q1.x + q1.y) + (q3.x + q3.y);
                af[mt][0] = h2u(p0);
                af[mt][1] = h2u(p1);
                af[mt][2] = h2u(p2);
                af[mt][3] = h2u(p3);
            }
            uint32_t bf[4][4];
            uint32_t base = cur + (row_off + (uint32_t)c * 8) * 4;
#pragma unroll
            for (int nn = 0; nn < 4; nn++)
                ldm_x4(bf[nn], base + (uint32_t)nn * (16u * STRIDE_W * 4u));
#pragma unroll
            for (int n = 0; n < 8; n++) {
                uint32_t b0 = bf[n >> 1][(n & 1) * 2];
                uint32_t b1 = bf[n >> 1][(n & 1) * 2 + 1];
                mma_f16(acc[0][n], af[0][0], af[0][1], af[0][2], af[0][3], b0, b1);
                mma_f16(acc[1][n], af[1][0], af[1][1], af[1][2], af[1][3], b0, b1);
            }
        }
    }
    __syncthreads();

    // ---- reduce across js groups (128 slots, stride 69, payload 64+4z) ----
    float* red = (float*)smem;
    int slot = mw * 32 + lane;
    float* accf = &acc[0][0][0];
#pragma unroll
    for (int src = 1; src < 4; src++) {
        if (js == src) {
#pragma unroll
            for (int i = 0; i < 64; i++) red[slot * 69 + i] = accf[i];
#pragma unroll
            for (int i = 0; i < 4; i++) red[slot * 69 + 64 + i] = z[i];
        }
        __syncthreads();
        if (js == 0) {
#pragma unroll
            for (int i = 0; i < 64; i++) accf[i] += red[slot * 69 + i];
#pragma unroll
            for (int i = 0; i < 4; i++) z[i] += red[slot * 69 + 64 + i];
        }
        __syncthreads();
    }

    // ---- epilogue (js == 0) ----
    if (js == 0) {
        // finish Z across the c4 quad (j-coverage per lane: 4 of 16 per chunk)
#pragma unroll
        for (int rr = 0; rr < 4; rr++) {
            z[rr] += __shfl_xor_sync(0xffffffffu, z[rr], 1);
            z[rr] += __shfl_xor_sync(0xffffffffu, z[rr], 2);
        }
        float inv0 = 1.f / z[0], inv1 = 1.f / z[1];
        float inv2 = 1.f / z[2], inv3 = 1.f / z[3];

        float* o0 = out + ((size_t)(b * NTOK + rbase)) * 64 + 2 * c4;
        float* o1 = o0 + 8 * 64;
        float* o2 = o0 + 16 * 64;
        float* o3 = o0 + 24 * 64;
#pragma unroll
        for (int n = 0; n < 8; n++) {
            float2 w0, w1, w2, w3;
            w0.x = eluf(acc[0][n][0] * inv0);
            w0.y = eluf(acc[0][n][1] * inv0);
            w1.x = eluf(acc[0][n][2] * inv1);
            w1.y = eluf(acc[0][n][3] * inv1);
            w2.x = eluf(acc[1][n][0] * inv2);
            w2.y = eluf(acc[1][n][1] * inv2);
            w3.x = eluf(acc[1][n][2] * inv3);
            w3.y = eluf(acc[1][n][3] * inv3);
            *(float2*)(o0 + n * 8) = w0;
            *(float2*)(o1 + n * 8) = w1;
            *(float2*)(o2 + n * 8) = w2;
            *(float2*)(o3 + n * 8) = w3;
        }
    }
}

// ---------------------------------------------------------------------------
extern "C" void kernel_launch(void* const* d_in, const int* in_sizes, int n_in,
                              void* d_out, int out_size) {
    const float* h = (const float*)d_in[0];
    const float* W = (const float*)d_in[1];
    const float* a = (const float*)d_in[2];
    float* out = (float*)d_out;

    cudaFuncSetAttribute(k3_attn, cudaFuncAttributeMaxDynamicSharedMemorySize,
                         SMEM3_TOTAL);

    k1_proj<<<(BATCH * NTOK) / 128, 256>>>(h, W, a);
    k2_prep<<<BATCH, 512>>>();
    dim3 g3(NTOK / 128, BATCH);
    k3_attn<<<g3, 512, SMEM3_TOTAL>>>(out);
}

// round 16
// speedup vs baseline: 1.0703x; 1.0693x over previous
#include <cuda_runtime.h>
#include <cuda_fp16.h>
#include <math.h>
#include <stdint.h>

#define BATCH 8
#define NTOK  2048
#define FDIM  64
#define ALPHA 0.2f

// ---------------- scratch (__device__ globals; no allocs allowed) ----------
__device__ __align__(16) __half g_WhT[BATCH * FDIM * NTOK];  // [b][o][j] fp16
__device__ float g_ssrc[BATCH * NTOK];
__device__ float g_sdst[BATCH * NTOK];
__device__ unsigned g_maxu[BATCH];      // order-preserving key of max(s_dst)
                                        // zero-init ok (0 < key(-FLT_MAX));
                                        // atomicMax idempotent across replays

__device__ __forceinline__ float eluf(float x) { return x > 0.f ? x : expm1f(x); }

__device__ __forceinline__ unsigned fkey(float f) {
    unsigned b = __float_as_uint(f);
    return (b & 0x80000000u) ? ~b : (b | 0x80000000u);
}
__device__ __forceinline__ float funkey(unsigned u) {
    return __uint_as_float((u & 0x80000000u) ? (u ^ 0x80000000u) : ~u);
}

__device__ __forceinline__ uint32_t smem_u32(const void* p) {
    uint32_t a;
    asm("{ .reg .u64 t; cvta.to.shared.u64 t, %1; cvt.u32.u64 %0, t; }" : "=r"(a) : "l"(p));
    return a;
}

__device__ __forceinline__ uint32_t h2u(__half2 h) {
    uint32_t r;
    asm("mov.b32 %0, %1;" : "=r"(r) : "r"(*(uint32_t*)&h));
    return r;
}

__device__ __forceinline__ void cp16(uint32_t dst, const void* src) {
    asm volatile("cp.async.cg.shared.global [%0], [%1], 16;" :: "r"(dst), "l"(src));
}
#define CP_COMMIT() asm volatile("cp.async.commit_group;" ::: "memory")
#define CP_WAIT0()  asm volatile("cp.async.wait_group 0;" ::: "memory")

__device__ __forceinline__ void mma_f16(float* d, uint32_t a0, uint32_t a1,
                                        uint32_t a2, uint32_t a3,
                                        uint32_t b0, uint32_t b1) {
    asm volatile(
        "mma.sync.aligned.m16n8k16.row.col.f32.f16.f16.f32 "
        "{%0,%1,%2,%3}, {%4,%5,%6,%7}, {%8,%9}, {%0,%1,%2,%3};"
        : "+f"(d[0]), "+f"(d[1]), "+f"(d[2]), "+f"(d[3])
        : "r"(a0), "r"(a1), "r"(a2), "r"(a3), "r"(b0), "r"(b1));
}

__device__ __forceinline__ void ldm_x4(uint32_t* r, uint32_t addr) {
    asm volatile("ldmatrix.sync.aligned.m8n8.x4.shared.b16 {%0,%1,%2,%3}, [%4];"
                 : "=r"(r[0]), "=r"(r[1]), "=r"(r[2]), "=r"(r[3]) : "r"(addr));
}

// ---------------------------------------------------------------------------
// Kernel 1: Wh via fp16 HMMA; exact fp32 scores s=h.(W@a); per-warp
// atomicMax of s_dst (replaces k2's reduction).  128 rows/CTA, 256 thr.
// ---------------------------------------------------------------------------
__global__ void __launch_bounds__(256) k1_proj(const float* __restrict__ h,
                                               const float* __restrict__ W,
                                               const float* __restrict__ a) {
    __shared__ float a_s[128];
    __shared__ float2 Wa_s[64];
    __shared__ __align__(16) __half WT_s[64 * 72];    // [o][k]
    __shared__ __align__(16) __half h_s[128 * 72];    // [j][k]
    __shared__ __align__(16) __half T_s[64 * 136];    // [o][j]

    int tid = threadIdx.x;
    int row0 = blockIdx.x * 128;
    int bb = row0 >> 11;
    int jbase = row0 & 2047;

    if (tid < 128) a_s[tid] = a[tid];
    __syncthreads();

    // ---- W transpose (fp16) + Wa = W @ a ----
    {
        int k = tid >> 2, qd = tid & 3;
        const float4* wr = (const float4*)(W + k * 64 + qd * 16);
        float pws = 0.f, pwd = 0.f;
#pragma unroll
        for (int f = 0; f < 4; f++) {
            float4 v = wr[f];
            int o = qd * 16 + f * 4;
            WT_s[(o + 0) * 72 + k] = __float2half(v.x);
            WT_s[(o + 1) * 72 + k] = __float2half(v.y);
            WT_s[(o + 2) * 72 + k] = __float2half(v.z);
            WT_s[(o + 3) * 72 + k] = __float2half(v.w);
            pws += v.x * a_s[o] + v.y * a_s[o + 1] + v.z * a_s[o + 2] + v.w * a_s[o + 3];
            pwd += v.x * a_s[64 + o] + v.y * a_s[65 + o] + v.z * a_s[66 + o] + v.w * a_s[67 + o];
        }
        pws += __shfl_xor_sync(0xffffffffu, pws, 1);
        pwd += __shfl_xor_sync(0xffffffffu, pwd, 1);
        pws += __shfl_xor_sync(0xffffffffu, pws, 2);
        pwd += __shfl_xor_sync(0xffffffffu, pwd, 2);
        if (qd == 0) Wa_s[k] = make_float2(pws, pwd);
    }

    // ---- h load (fp32) ----
    int r = tid >> 1, hf = tid & 1;
    float4 hv[8];
    {
        const float4* hrow = (const float4*)(h + (size_t)(row0 + r) * 64 + hf * 32);
#pragma unroll
        for (int f = 0; f < 8; f++) hv[f] = hrow[f];
    }
    __syncthreads();

    // ---- exact dots + fp16 h_s store + warp max of s_dst ----
    {
        float ps = 0.f, pd = 0.f;
        __half2* hs2 = (__half2*)(h_s + r * 72 + hf * 32);
#pragma unroll
        for (int f = 0; f < 8; f++) {
            float4 v = hv[f];
            int k = hf * 32 + f * 4;
            float2 w0 = Wa_s[k], w1 = Wa_s[k + 1], w2 = Wa_s[k + 2], w3 = Wa_s[k + 3];
            ps += v.x * w0.x + v.y * w1.x + v.z * w2.x + v.w * w3.x;
            pd += v.x * w0.y + v.y * w1.y + v.z * w2.y + v.w * w3.y;
            hs2[f * 2]     = __floats2half2_rn(v.x, v.y);
            hs2[f * 2 + 1] = __floats2half2_rn(v.z, v.w);
        }
        ps += __shfl_xor_sync(0xffffffffu, ps, 1);
        pd += __shfl_xor_sync(0xffffffffu, pd, 1);
        if (hf == 0) {
            g_ssrc[row0 + r] = ps;
            g_sdst[row0 + r] = pd;
        }
        // warp max of pd (all lanes hold valid row sums after the xor-1 sum)
        float wm = pd;
#pragma unroll
        for (int o = 2; o < 32; o <<= 1)
            wm = fmaxf(wm, __shfl_xor_sync(0xffffffffu, wm, o));
        wm = fmaxf(wm, __shfl_xor_sync(0xffffffffu, wm, 1));
        if ((tid & 31) == 0) atomicMax(&g_maxu[bb], fkey(wm));
    }
    __syncthreads();

    // ---- MMA: 8 warps x 16 rows ----
    int w = tid >> 5, lane = tid & 31;
    uint32_t hs_b = smem_u32(h_s);
    uint32_t wt_b = smem_u32(WT_s);
    uint32_t aoff = ((w * 16 + ((lane >> 3) & 1) * 8 + (lane & 7)) * 36 +
                     ((lane >> 4) & 1) * 4) * 4;
    uint32_t boff = ((((lane >> 4) & 1) * 8 + (lane & 7)) * 36 +
                     ((lane >> 3) & 1) * 4) * 4;

    float acc[8][4];
#pragma unroll
    for (int n = 0; n < 8; n++)
#pragma unroll
        for (int i = 0; i < 4; i++) acc[n][i] = 0.f;

#pragma unroll
    for (int kk = 0; kk < 4; kk++) {
        uint32_t av[4];
        ldm_x4(av, hs_b + aoff + kk * 32);
#pragma unroll
        for (int nn = 0; nn < 4; nn++) {
            uint32_t bv[4];
            ldm_x4(bv, wt_b + boff + nn * 2304 + kk * 32);
            mma_f16(acc[2 * nn],     av[0], av[1], av[2], av[3], bv[0], bv[1]);
            mma_f16(acc[2 * nn + 1], av[0], av[1], av[2], av[3], bv[2], bv[3]);
        }
    }

    // ---- transpose acc -> T_s[o][j] (stride 136 halfs) ----
    {
        int q = lane >> 2, c4 = lane & 3;
        int jr = w * 16 + q;
#pragma unroll
        for (int n = 0; n < 8; n++) {
            int o = n * 8 + 2 * c4;
            T_s[o * 136 + jr]           = __float2half(acc[n][0]);
            T_s[(o + 1) * 136 + jr]     = __float2half(acc[n][1]);
            T_s[o * 136 + jr + 8]       = __float2half(acc[n][2]);
            T_s[(o + 1) * 136 + jr + 8] = __float2half(acc[n][3]);
        }
    }
    __syncthreads();

    // ---- coalesced WhT store ----
    {
        const uint4* T4 = (const uint4*)T_s;          // row stride 17 uint4
        uint4* dst = (uint4*)(g_WhT + (size_t)bb * FDIM * NTOK + jbase);
#pragma unroll
        for (int it = 0; it < 4; it++) {
            int idx = tid + it * 256;
            int o = idx >> 4, u4 = idx & 15;
            dst[o * 256 + u4] = T4[o * 17 + u4];
        }
    }
}

// ---------------------------------------------------------------------------
// Kernel 3: fused attention.  u/v fp16 tables built in-CTA (k2 eliminated);
// fp32 Z from p-words; 256-j tiles; cp.async; interleaved ldm+mma (low regs).
//   128 CTAs, 512 thr = 4 m-warps x 4 j-split.
// ---------------------------------------------------------------------------
#define STRIDE_W  132                      // words per o-row (256 halfs + pad)
#define TBB       (64 * STRIDE_W * 4)      // 33792 B per buffer
#define UOFF      (2 * TBB)
#define VOFF      (UOFF + 4096)
#define SMEM3_TOTAL (VOFF + 4096)

__global__ void __launch_bounds__(512, 1) k3_attn(float* __restrict__ out) {
    extern __shared__ char smem[];
    uint32_t sb = smem_u32(smem);
    __half* u_h = (__half*)(smem + UOFF);
    __half* v_h = (__half*)(smem + VOFF);
    const __half2* u2_s = (const __half2*)(smem + UOFF);
    const __half2* v2_s = (const __half2*)(smem + VOFF);

    int tid = threadIdx.x;
    int lane = tid & 31;
    int wid = tid >> 5;
    int mw = wid & 3, js = wid >> 2;
    int b = blockIdx.y;
    int i0 = blockIdx.x * 128;

    const uint4* WhT4 = (const uint4*)(g_WhT + (size_t)b * FDIM * NTOK);
    int so = tid >> 5, su = tid & 31;

    // prologue: issue tile 0 via cp.async FIRST (overlaps the exp work below)
#pragma unroll
    for (int it = 0; it < 4; it++) {
        int o = so + it * 16;
        cp16(sb + (uint32_t)(o * STRIDE_W + su * 4) * 4, WhT4 + o * 256 + su);
    }
    CP_COMMIT();

    float M = funkey(g_maxu[b]);

    // u/v tables: u~=e^(sd-M), v~=e^(a(sd-M)) in (0,1] -> fp16-safe
    for (int i = tid; i < NTOK; i += 512) {
        float d = g_sdst[b * NTOK + i] - M;
        u_h[i] = __float2half(expf(d));
        v_h[i] = __float2half(expf(ALPHA * d));
    }

    int q = lane >> 2, c4 = lane & 3;
    int rbase = i0 + mw * 32 + q;
    __half2 A2[4], B2[4];
#pragma unroll
    for (int rr = 0; rr < 4; rr++) {
        float t = g_ssrc[b * NTOK + rbase + rr * 8] + M;
        float mi = t > 0.f ? t : ALPHA * t;
        A2[rr] = __float2half2_rn(expf(t - mi));
        B2[rr] = __float2half2_rn(expf(ALPHA * t - mi));
    }

    float acc[2][8][4];
    float z[4] = {0.f, 0.f, 0.f, 0.f};
#pragma unroll
    for (int mt = 0; mt < 2; mt++)
#pragma unroll
        for (int n = 0; n < 8; n++)
#pragma unroll
            for (int i = 0; i < 4; i++) acc[mt][n][i] = 0.f;

    uint32_t row_off = ((((lane >> 4) & 1) * 8 + (lane & 7)) * (uint32_t)STRIDE_W) +
                       ((lane >> 3) & 1) * 4u;

    for (int t = 0; t < 8; t++) {
        CP_WAIT0();
        __syncthreads();                    // tile t ready; u/v ready (t==0)

        if (t < 7) {
            uint32_t nb = sb + ((t + 1) & 1) * (uint32_t)TBB;
#pragma unroll
            for (int it = 0; it < 4; it++) {
                int o = so + it * 16;
                cp16(nb + (uint32_t)(o * STRIDE_W + su * 4) * 4,
                     WhT4 + o * 256 + (t + 1) * 32 + su);
            }
            CP_COMMIT();
        }

        uint32_t cur = sb + (t & 1) * (uint32_t)TBB;
#pragma unroll
        for (int cc = 0; cc < 4; cc++) {
            int c = js * 4 + cc;
            int cb2 = t * 128 + c * 8;
            __half2 ua = u2_s[cb2 + c4];
            __half2 ub = u2_s[cb2 + 4 + c4];
            __half2 va = v2_s[cb2 + c4];
            __half2 vb = v2_s[cb2 + 4 + c4];
            uint32_t af[2][4];
#pragma unroll
            for (int mt = 0; mt < 2; mt++) {
                int r0 = mt * 2, r1 = mt * 2 + 1;
                __half2 p0 = __hmax2(__hmul2(A2[r0], ua), __hmul2(B2[r0], va));
                __half2 p1 = __hmax2(__hmul2(A2[r1], ua), __hmul2(B2[r1], va));
                __half2 p2 = __hmax2(__hmul2(A2[r0], ub), __hmul2(B2[r0], vb));
                __half2 p3 = __hmax2(__hmul2(A2[r1], ub), __hmul2(B2[r1], vb));
                float2 q0 = __half22float2(p0), q2 = __half22float2(p2);
                z[r0] += (q0.x + q0.y) + (q2.x + q2.y);
                float2 q1 = __half22float2(p1), q3 = __half22float2(p3);
                z[r1] += (q1.x + q1.y) + (q3.x + q3.y);
                af[mt][0] = h2u(p0);
                af[mt][1] = h2u(p1);
                af[mt][2] = h2u(p2);
                af[mt][3] = h2u(p3);
            }
            uint32_t base = cur + (row_off + (uint32_t)c * 8) * 4;
#pragma unroll
            for (int nn = 0; nn < 4; nn++) {
                uint32_t bv[4];                 // only 4 B regs live
                ldm_x4(bv, base + (uint32_t)nn * (16u * STRIDE_W * 4u));
                mma_f16(acc[0][2 * nn],     af[0][0], af[0][1], af[0][2], af[0][3], bv[0], bv[1]);
                mma_f16(acc[1][2 * nn],     af[1][0], af[1][1], af[1][2], af[1][3], bv[0], bv[1]);
                mma_f16(acc[0][2 * nn + 1], af[0][0], af[0][1], af[0][2], af[0][3], bv[2], bv[3]);
                mma_f16(acc[1][2 * nn + 1], af[1][0], af[1][1], af[1][2], af[1][3], bv[2], bv[3]);
            }
        }
    }
    __syncthreads();

    // ---- reduce across js groups (128 slots, stride 69, payload 64+4z) ----
    float* red = (float*)smem;
    int slot = mw * 32 + lane;
    float* accf = &acc[0][0][0];
#pragma unroll
    for (int src = 1; src < 4; src++) {
        if (js == src) {
#pragma unroll
            for (int i = 0; i < 64; i++) red[slot * 69 + i] = accf[i];
#pragma unroll
            for (int i = 0; i < 4; i++) red[slot * 69 + 64 + i] = z[i];
        }
        __syncthreads();
        if (js == 0) {
#pragma unroll
            for (int i = 0; i < 64; i++) accf[i] += red[slot * 69 + i];
#pragma unroll
            for (int i = 0; i < 4; i++) z[i] += red[slot * 69 + 64 + i];
        }
        __syncthreads();
    }

    // ---- epilogue (js == 0) ----
    if (js == 0) {
#pragma unroll
        for (int rr = 0; rr < 4; rr++) {
            z[rr] += __shfl_xor_sync(0xffffffffu, z[rr], 1);
            z[rr] += __shfl_xor_sync(0xffffffffu, z[rr], 2);
        }
        float inv0 = 1.f / z[0], inv1 = 1.f / z[1];
        float inv2 = 1.f / z[2], inv3 = 1.f / z[3];

        float* o0 = out + ((size_t)(b * NTOK + rbase)) * 64 + 2 * c4;
        float* o1 = o0 + 8 * 64;
        float* o2 = o0 + 16 * 64;
        float* o3 = o0 + 24 * 64;
#pragma unroll
        for (int n = 0; n < 8; n++) {
            float2 w0, w1, w2, w3;
            w0.x = eluf(acc[0][n][0] * inv0);
            w0.y = eluf(acc[0][n][1] * inv0);
            w1.x = eluf(acc[0][n][2] * inv1);
            w1.y = eluf(acc[0][n][3] * inv1);
            w2.x = eluf(acc[1][n][0] * inv2);
            w2.y = eluf(acc[1][n][1] * inv2);
            w3.x = eluf(acc[1][n][2] * inv3);
            w3.y = eluf(acc[1][n][3] * inv3);
            *(float2*)(o0 + n * 8) = w0;
            *(float2*)(o1 + n * 8) = w1;
            *(float2*)(o2 + n * 8) = w2;
            *(float2*)(o3 + n * 8) = w3;
        }
    }
}

// ---------------------------------------------------------------------------
extern "C" void kernel_launch(void* const* d_in, const int* in_sizes, int n_in,
                              void* d_out, int out_size) {
    const float* h = (const float*)d_in[0];
    const float* W = (const float*)d_in[1];
    const float* a = (const float*)d_in[2];
    float* out = (float*)d_out;

    cudaFuncSetAttribute(k3_attn, cudaFuncAttributeMaxDynamicSharedMemorySize,
                         SMEM3_TOTAL);

    k1_proj<<<(BATCH * NTOK) / 128, 256>>>(h, W, a);
    dim3 g3(NTOK / 128, BATCH);
    k3_attn<<<g3, 512, SMEM3_TOTAL>>>(out);
}